// round 1
// baseline (speedup 1.0000x reference)
#include <cuda_runtime.h>
#include <math.h>

#define B_      8
#define TNEW    512
#define DMODEL  1024
#define H_      16
#define DH      64
#define CACHED  2048
#define TTOTAL  2560
#define MROWS   (B_*TNEW)      // 4096
#define QKVN    3072

#define OFF_K   (MROWS*DMODEL)               // 4194304
#define OFF_V   (OFF_K + B_*H_*TTOTAL*DH)    // 25165824
#define OFF_LEN (OFF_V + B_*H_*TTOTAL*DH)    // 46137344

// Scratch (allocation-free rule: __device__ globals)
__device__ float g_qkv[MROWS*QKVN];     // raw q|k|v projections [4096][3072]
__device__ float g_q  [B_*H_*TNEW*DH];  // roped q, [BH][T][DH]
__device__ float g_ctx[MROWS*DMODEL];   // attention context [4096][1024]
__device__ int   g_counts[B_];
__device__ int   g_totals[B_];

// ---------------------------------------------------------------------------
// Kernel 1: derive new_counts from valid_new_mask (dtype-probed), totals
// ---------------------------------------------------------------------------
__global__ void k_setup(const unsigned char* __restrict__ mask,
                        const int* __restrict__ past_len,
                        float* __restrict__ out_len)
{
    int b = blockIdx.x;
    int lane = threadIdx.x;
    // dtype probe: element (7,1) is guaranteed true (last batch item full).
    // 1-byte layout -> byte[7*512+1] nonzero. 4-byte layouts (int32/float32)
    // -> that byte is byte#1 of element 896 (value 0 or 1 / 0.0f or 1.0f) = 0.
    bool bytemode = (mask[7*TNEW + 1] != 0);
    int cnt = 0;
    for (int t = lane; t < TNEW; t += 32) {
        int nz;
        if (bytemode) nz = (mask[b*TNEW + t] != 0);
        else          nz = (((const int*)mask)[b*TNEW + t] != 0); // works for i32 & f32 bits
        cnt += nz;
    }
    #pragma unroll
    for (int o = 16; o; o >>= 1) cnt += __shfl_xor_sync(0xffffffffu, cnt, o);
    if (lane == 0) {
        g_counts[b] = cnt;
        int tot = past_len[b] + cnt;
        g_totals[b] = tot;
        out_len[b] = (float)tot;
    }
}

// ---------------------------------------------------------------------------
// Accurate RoPE angles even under --use_fast_math: fp64 range reduction,
// then fp32 sincos on the reduced argument.
// ---------------------------------------------------------------------------
__device__ __forceinline__ void rope_sc(int pos, float fi, float& sn, float& cs)
{
    double f = (double)pos * (double)fi;
    double k = floor(f * 0.15915494309189535);           // / (2*pi)
    float fr = (float)(f - k * 6.283185307179586);
    sincosf(fr, &sn, &cs);
}

// ---------------------------------------------------------------------------
// Kernel 2: QKV projection GEMM  C[4096][3072] = X[4096][1024] @ W^T + bias
// 128x128 block tile, K-tile 8, 256 threads, 8x8 per thread.
// ---------------------------------------------------------------------------
__global__ __launch_bounds__(256) void k_gemm_qkv(
    const float* __restrict__ X,
    const float* __restrict__ Wq, const float* __restrict__ Wk, const float* __restrict__ Wv,
    const float* __restrict__ bq, const float* __restrict__ bk, const float* __restrict__ bv)
{
    __shared__ float As[8][136];
    __shared__ float Bs[8][136];
    int bm = blockIdx.y * 128;
    int bn = blockIdx.x * 128;            // global col in [0,3072)
    int seg = bn >> 10;                   // 0=q, 1=k, 2=v (block never straddles)
    const float* W    = (seg == 0) ? Wq : ((seg == 1) ? Wk : Wv);
    const float* bias = (seg == 0) ? bq : ((seg == 1) ? bk : bv);
    int nl = bn & 1023;
    int tid = threadIdx.x;
    int tx = tid & 15, ty = tid >> 4;
    int lrow = tid >> 1;
    int lk = (tid & 1) * 4;
    const float* Ap = X + (size_t)(bm + lrow) * DMODEL + lk;
    const float* Wp = W + (size_t)(nl + lrow) * DMODEL + lk;

    float acc[8][8];
    #pragma unroll
    for (int i = 0; i < 8; i++)
        #pragma unroll
        for (int j = 0; j < 8; j++) acc[i][j] = 0.f;

    for (int k0 = 0; k0 < DMODEL; k0 += 8) {
        float4 av = *(const float4*)(Ap + k0);
        float4 wv = *(const float4*)(Wp + k0);
        As[lk+0][lrow] = av.x; As[lk+1][lrow] = av.y;
        As[lk+2][lrow] = av.z; As[lk+3][lrow] = av.w;
        Bs[lk+0][lrow] = wv.x; Bs[lk+1][lrow] = wv.y;
        Bs[lk+2][lrow] = wv.z; Bs[lk+3][lrow] = wv.w;
        __syncthreads();
        #pragma unroll
        for (int kk = 0; kk < 8; kk++) {
            float a[8], bb[8];
            *(float4*)(a)    = *(const float4*)&As[kk][ty*8];
            *(float4*)(a+4)  = *(const float4*)&As[kk][ty*8+4];
            *(float4*)(bb)   = *(const float4*)&Bs[kk][tx*8];
            *(float4*)(bb+4) = *(const float4*)&Bs[kk][tx*8+4];
            #pragma unroll
            for (int i = 0; i < 8; i++)
                #pragma unroll
                for (int j = 0; j < 8; j++)
                    acc[i][j] = fmaf(a[i], bb[j], acc[i][j]);
        }
        __syncthreads();
    }
    #pragma unroll
    for (int i = 0; i < 8; i++) {
        int m = bm + ty*8 + i;
        float* dst = g_qkv + (size_t)m * QKVN + bn + tx*8;
        float r[8];
        #pragma unroll
        for (int j = 0; j < 8; j++) r[j] = acc[i][j] + bias[(bn + tx*8 + j) & 1023];
        *(float4*)dst      = *(float4*)r;
        *(float4*)(dst+4)  = *(float4*)(r+4);
    }
}

// ---------------------------------------------------------------------------
// Kernel 3a: RoPE on q -> g_q [BH][T][DH] (invalid tokens zeroed)
// thread handles dim pair (i, i+32)
// ---------------------------------------------------------------------------
__global__ __launch_bounds__(256) void k_rope_q(const float* __restrict__ invf,
                                                const int* __restrict__ past_len)
{
    int bh = blockIdx.y; int b = bh >> 4; int h = bh & 15;
    int gid = blockIdx.x * 256 + threadIdx.x;
    int i = gid & 31; int t = gid >> 5;
    int cnt = g_counts[b];
    float o0 = 0.f, o1 = 0.f;
    if (t < cnt) {
        int pos = past_len[b] + t;
        float sn, cs; rope_sc(pos, invf[i], sn, cs);
        size_t base = (size_t)(b*TNEW + t) * QKVN + h*DH;
        float x0 = g_qkv[base + i];
        float x1 = g_qkv[base + i + 32];
        o0 = x0*cs - x1*sn;
        o1 = x1*cs + x0*sn;
    }
    size_t qb = ((size_t)bh*TNEW + t) * DH;
    g_q[qb + i]      = o0;
    g_q[qb + i + 32] = o1;
}

// ---------------------------------------------------------------------------
// Kernel 3b: assemble k_total / v_total in d_out (copy cache, scatter roped
// new keys / new values, zero tail)
// ---------------------------------------------------------------------------
__global__ __launch_bounds__(256) void k_assemble_kv(
    const float* __restrict__ pastk, const float* __restrict__ pastv,
    const float* __restrict__ invf, const int* __restrict__ past_len,
    float* __restrict__ out)
{
    int bh = blockIdx.y; int b = bh >> 4; int h = bh & 15;
    int gid = blockIdx.x * 256 + threadIdx.x;
    int i = gid & 31; int s = gid >> 5;
    int pl = past_len[b]; int tot = g_totals[b];
    float k0, k1, v0, v1;
    if (s < pl) {
        size_t base = ((size_t)bh*CACHED + s) * DH;
        k0 = pastk[base + i]; k1 = pastk[base + i + 32];
        v0 = pastv[base + i]; v1 = pastv[base + i + 32];
    } else if (s < tot) {
        int t = s - pl;
        size_t m = (size_t)(b*TNEW + t) * QKVN;
        float sn, cs; rope_sc(s, invf[i], sn, cs);
        float x0 = g_qkv[m + 1024 + h*DH + i];
        float x1 = g_qkv[m + 1024 + h*DH + i + 32];
        k0 = x0*cs - x1*sn;
        k1 = x1*cs + x0*sn;
        v0 = g_qkv[m + 2048 + h*DH + i];
        v1 = g_qkv[m + 2048 + h*DH + i + 32];
    } else {
        k0 = k1 = v0 = v1 = 0.f;
    }
    size_t base = ((size_t)bh*TTOTAL + s) * DH;
    out[OFF_K + base + i]      = k0;
    out[OFF_K + base + i + 32] = k1;
    out[OFF_V + base + i]      = v0;
    out[OFF_V + base + i + 32] = v1;
}

// ---------------------------------------------------------------------------
// Kernel 4: flash attention. Block = (bh, qblock of 64 rows). 256 threads,
// 4x4 per-thread tiles, online softmax, key tiles of 64.
// ---------------------------------------------------------------------------
#define AST 68   // padded smem stride (16B-aligned, conflict-reducing)

__global__ __launch_bounds__(256) void k_attn(const float* __restrict__ kvout)
{
    extern __shared__ float sm[];
    float* Qt   = sm;              // Qt[d*AST + r]   (transposed Q tile)
    float* KV   = sm + 64*AST;     // K: [d*AST + c] transposed ; V: [c*AST + d]
    float* Ps   = sm + 2*64*AST;   // Ps[c*AST + r]   (transposed P tile)
    float* redm = sm + 3*64*AST;   // redm[tx*AST + r]
    float* redl = redm + 16*AST;

    int bh = blockIdx.x;
    int b = bh >> 4;
    int qb = blockIdx.y << 6;
    int tid = threadIdx.x;
    int tx = tid & 15, ty = tid >> 4;

    // load Q tile transposed
    {
        int r = tid >> 2, t4 = tid & 3;
        const float* qp = g_q + ((size_t)bh*TNEW + qb + r) * DH + t4*16;
        #pragma unroll
        for (int q = 0; q < 4; q++) {
            float4 v = *(const float4*)(qp + q*4);
            int d = t4*16 + q*4;
            Qt[(d+0)*AST + r] = v.x; Qt[(d+1)*AST + r] = v.y;
            Qt[(d+2)*AST + r] = v.z; Qt[(d+3)*AST + r] = v.w;
        }
    }
    float accO[4][4] = {};
    float mrow[4], lrow[4];
    #pragma unroll
    for (int i = 0; i < 4; i++) { mrow[i] = -1e30f; lrow[i] = 0.f; }
    int tot = g_totals[b];
    int nkb = (tot + 63) >> 6;
    const float* kbase = kvout + OFF_K + (size_t)bh*TTOTAL*DH;
    const float* vbase = kvout + OFF_V + (size_t)bh*TTOTAL*DH;
    __syncthreads();  // Qt ready

    for (int kb = 0; kb < nkb; kb++) {
        // load K tile transposed (previous iter's smem reads done: loop-end sync)
        {
            int r = tid >> 2, t4 = tid & 3;
            const float* kp = kbase + (size_t)(kb*64 + r) * DH + t4*16;
            #pragma unroll
            for (int q = 0; q < 4; q++) {
                float4 v = *(const float4*)(kp + q*4);
                int d = t4*16 + q*4;
                KV[(d+0)*AST + r] = v.x; KV[(d+1)*AST + r] = v.y;
                KV[(d+2)*AST + r] = v.z; KV[(d+3)*AST + r] = v.w;
            }
        }
        __syncthreads();

        // S = Q K^T
        float sacc[4][4] = {};
        #pragma unroll 16
        for (int d = 0; d < 64; d++) {
            float a[4], bb[4];
            *(float4*)a  = *(const float4*)&Qt[d*AST + ty*4];
            *(float4*)bb = *(const float4*)&KV[d*AST + tx*4];
            #pragma unroll
            for (int i = 0; i < 4; i++)
                #pragma unroll
                for (int j = 0; j < 4; j++)
                    sacc[i][j] = fmaf(a[i], bb[j], sacc[i][j]);
        }

        // scale + mask, local row max
        float lmax[4];
        #pragma unroll
        for (int i = 0; i < 4; i++) lmax[i] = -1e30f;
        int cb0 = kb*64 + tx*4;
        #pragma unroll
        for (int j = 0; j < 4; j++) {
            bool valid = (cb0 + j) < tot;
            #pragma unroll
            for (int i = 0; i < 4; i++) {
                float sv = valid ? sacc[i][j] * 0.125f : -1e30f;
                sacc[i][j] = sv;
                lmax[i] = fmaxf(lmax[i], sv);
            }
        }
        #pragma unroll
        for (int i = 0; i < 4; i++) redm[tx*AST + ty*4 + i] = lmax[i];
        __syncthreads();

        float mnew[4], esc[4];
        #pragma unroll
        for (int i = 0; i < 4; i++) {
            int r = ty*4 + i;
            float mx = -1e30f;
            #pragma unroll
            for (int j = 0; j < 16; j++) mx = fmaxf(mx, redm[j*AST + r]);
            mnew[i] = fmaxf(mrow[i], mx);
            esc[i]  = __expf(mrow[i] - mnew[i]);
            mrow[i] = mnew[i];
        }
        float lsum[4] = {};
        #pragma unroll
        for (int i = 0; i < 4; i++) {
            #pragma unroll
            for (int j = 0; j < 4; j++) {
                float p = __expf(sacc[i][j] - mnew[i]);
                lsum[i] += p;
                Ps[(tx*4 + j)*AST + ty*4 + i] = p;
            }
            #pragma unroll
            for (int j = 0; j < 4; j++) accO[i][j] *= esc[i];
        }
        #pragma unroll
        for (int i = 0; i < 4; i++) redl[tx*AST + ty*4 + i] = lsum[i];
        __syncthreads();  // Ps + redl visible; all K reads of KV complete

        #pragma unroll
        for (int i = 0; i < 4; i++) {
            int r = ty*4 + i;
            float ssum = 0.f;
            #pragma unroll
            for (int j = 0; j < 16; j++) ssum += redl[j*AST + r];
            lrow[i] = lrow[i]*esc[i] + ssum;
        }
        // load V tile (natural layout)
        {
            int r = tid >> 2, t4 = tid & 3;
            const float* vp = vbase + (size_t)(kb*64 + r) * DH + t4*16;
            #pragma unroll
            for (int q = 0; q < 4; q++) {
                float4 v = *(const float4*)(vp + q*4);
                *(float4*)&KV[r*AST + t4*16 + q*4] = v;
            }
        }
        __syncthreads();

        // O += P V
        #pragma unroll 8
        for (int c = 0; c < 64; c++) {
            float a[4], bb[4];
            *(float4*)a  = *(const float4*)&Ps[c*AST + ty*4];
            *(float4*)bb = *(const float4*)&KV[c*AST + tx*4];
            #pragma unroll
            for (int i = 0; i < 4; i++)
                #pragma unroll
                for (int j = 0; j < 4; j++)
                    accO[i][j] = fmaf(a[i], bb[j], accO[i][j]);
        }
        __syncthreads();  // protect Ps/KV before next iteration overwrites
    }

    // finalize: O /= l ; write ctx [B,T,H*DH]
    #pragma unroll
    for (int i = 0; i < 4; i++) {
        int r = qb + ty*4 + i;
        float inv = 1.f / lrow[i];
        float o[4];
        #pragma unroll
        for (int j = 0; j < 4; j++) o[j] = accO[i][j] * inv;
        *(float4*)(g_ctx + ((size_t)b*TNEW + r) * DMODEL + (bh & 15)*DH + tx*4) = *(float4*)o;
    }
}

// ---------------------------------------------------------------------------
// Kernel 5: output projection + valid-token mask
// ---------------------------------------------------------------------------
__global__ __launch_bounds__(256) void k_gemm_out(
    const float* __restrict__ Wo, const float* __restrict__ bo,
    float* __restrict__ out)
{
    __shared__ float As[8][136];
    __shared__ float Bs[8][136];
    int bm = blockIdx.y * 128;
    int bn = blockIdx.x * 128;
    int tid = threadIdx.x;
    int tx = tid & 15, ty = tid >> 4;
    int lrow = tid >> 1;
    int lk = (tid & 1) * 4;
    const float* Ap = g_ctx + (size_t)(bm + lrow) * DMODEL + lk;
    const float* Wp = Wo    + (size_t)(bn + lrow) * DMODEL + lk;

    float acc[8][8];
    #pragma unroll
    for (int i = 0; i < 8; i++)
        #pragma unroll
        for (int j = 0; j < 8; j++) acc[i][j] = 0.f;

    for (int k0 = 0; k0 < DMODEL; k0 += 8) {
        float4 av = *(const float4*)(Ap + k0);
        float4 wv = *(const float4*)(Wp + k0);
        As[lk+0][lrow] = av.x; As[lk+1][lrow] = av.y;
        As[lk+2][lrow] = av.z; As[lk+3][lrow] = av.w;
        Bs[lk+0][lrow] = wv.x; Bs[lk+1][lrow] = wv.y;
        Bs[lk+2][lrow] = wv.z; Bs[lk+3][lrow] = wv.w;
        __syncthreads();
        #pragma unroll
        for (int kk = 0; kk < 8; kk++) {
            float a[8], bb[8];
            *(float4*)(a)    = *(const float4*)&As[kk][ty*8];
            *(float4*)(a+4)  = *(const float4*)&As[kk][ty*8+4];
            *(float4*)(bb)   = *(const float4*)&Bs[kk][tx*8];
            *(float4*)(bb+4) = *(const float4*)&Bs[kk][tx*8+4];
            #pragma unroll
            for (int i = 0; i < 8; i++)
                #pragma unroll
                for (int j = 0; j < 8; j++)
                    acc[i][j] = fmaf(a[i], bb[j], acc[i][j]);
        }
        __syncthreads();
    }
    #pragma unroll
    for (int i = 0; i < 8; i++) {
        int m = bm + ty*8 + i;
        int b = m >> 9, t = m & 511;
        float msk = (t < g_counts[b]) ? 1.f : 0.f;
        float* dst = out + (size_t)m * DMODEL + bn + tx*8;
        float r[8];
        #pragma unroll
        for (int j = 0; j < 8; j++) r[j] = (acc[i][j] + bo[bn + tx*8 + j]) * msk;
        *(float4*)dst     = *(float4*)r;
        *(float4*)(dst+4) = *(float4*)(r+4);
    }
}

// ---------------------------------------------------------------------------
extern "C" void kernel_launch(void* const* d_in, const int* in_sizes, int n_in,
                              void* d_out, int out_size)
{
    const float* x     = (const float*)d_in[0];
    const float* invf  = (const float*)d_in[1];
    const float* pastk = (const float*)d_in[2];
    const float* pastv = (const float*)d_in[3];
    const float* Wq    = (const float*)d_in[4];
    const float* bq    = (const float*)d_in[5];
    const float* Wk    = (const float*)d_in[6];
    const float* bk    = (const float*)d_in[7];
    const float* Wv    = (const float*)d_in[8];
    const float* bv    = (const float*)d_in[9];
    const float* Wo    = (const float*)d_in[10];
    const float* bo    = (const float*)d_in[11];
    // d_in[12] key_padding_mask: not needed (valid region = [0, total_len))
    const int* past_len = (const int*)d_in[13];
    const unsigned char* vmask = (const unsigned char*)d_in[14];
    float* out = (float*)d_out;

    k_setup<<<B_, 32>>>(vmask, past_len, out + OFF_LEN);
    k_gemm_qkv<<<dim3(QKVN/128, MROWS/128), 256>>>(x, Wq, Wk, Wv, bq, bk, bv);
    k_rope_q<<<dim3(TNEW*32/256, B_*H_), 256>>>(invf, past_len);
    k_assemble_kv<<<dim3(TTOTAL*32/256, B_*H_), 256>>>(pastk, pastv, invf, past_len, out);

    int smem = (3*64*AST + 2*16*AST) * 4;  // 60928 bytes
    cudaFuncSetAttribute(k_attn, cudaFuncAttributeMaxDynamicSharedMemorySize, smem);
    k_attn<<<dim3(B_*H_, TNEW/64), 256, smem>>>(out);

    k_gemm_out<<<dim3(DMODEL/128, MROWS/128), 256>>>(Wo, bo, out);
}

// round 3
// speedup vs baseline: 3.1030x; 3.1030x over previous
#include <cuda_runtime.h>
#include <math.h>

#define B_      8
#define TNEW    512
#define DMODEL  1024
#define H_      16
#define DH      64
#define CACHED  2048
#define TTOTAL  2560
#define MROWS   (B_*TNEW)      // 4096
#define QKVN    3072

#define OFF_K   (MROWS*DMODEL)               // 4194304
#define OFF_V   (OFF_K + B_*H_*TTOTAL*DH)    // 25165824
#define OFF_LEN (OFF_V + B_*H_*TTOTAL*DH)    // 46137344

// Scratch (allocation-free rule: __device__ globals)
__device__ float g_qkv[MROWS*QKVN];     // raw q|k|v projections [4096][3072]
__device__ float g_q  [B_*H_*TNEW*DH];  // roped q, [BH][T][DH]
__device__ float g_ctx[MROWS*DMODEL];   // attention context [4096][1024]
__device__ int   g_counts[B_];
__device__ int   g_totals[B_];

// ---------------------------------------------------------------------------
// tf32 helpers
// ---------------------------------------------------------------------------
__device__ __forceinline__ float t32(float f) {
    unsigned u;
    asm("cvt.rna.tf32.f32 %0, %1;" : "=r"(u) : "f"(f));
    return __uint_as_float(u);
}
__device__ __forceinline__ unsigned U(float f) { return __float_as_uint(f); }

__device__ __forceinline__ void mma8(float* c, const unsigned* a, const unsigned* b) {
    asm volatile(
        "mma.sync.aligned.m16n8k8.row.col.f32.tf32.tf32.f32 "
        "{%0,%1,%2,%3},{%4,%5,%6,%7},{%8,%9},{%0,%1,%2,%3};"
        : "+f"(c[0]), "+f"(c[1]), "+f"(c[2]), "+f"(c[3])
        : "r"(a[0]), "r"(a[1]), "r"(a[2]), "r"(a[3]), "r"(b[0]), "r"(b[1]));
}

// ---------------------------------------------------------------------------
// Kernel 1: derive new_counts from valid_new_mask (dtype-probed), totals
// ---------------------------------------------------------------------------
__global__ void k_setup(const unsigned char* __restrict__ mask,
                        const int* __restrict__ past_len,
                        float* __restrict__ out_len)
{
    int b = blockIdx.x;
    int lane = threadIdx.x;
    bool bytemode = (mask[7*TNEW + 1] != 0);
    int cnt = 0;
    for (int t = lane; t < TNEW; t += 32) {
        int nz;
        if (bytemode) nz = (mask[b*TNEW + t] != 0);
        else          nz = (((const int*)mask)[b*TNEW + t] != 0);
        cnt += nz;
    }
    #pragma unroll
    for (int o = 16; o; o >>= 1) cnt += __shfl_xor_sync(0xffffffffu, cnt, o);
    if (lane == 0) {
        g_counts[b] = cnt;
        int tot = past_len[b] + cnt;
        g_totals[b] = tot;
        out_len[b] = (float)tot;
    }
}

// ---------------------------------------------------------------------------
// Accurate RoPE angles (fp64 range reduction, fp32 sincos)
// ---------------------------------------------------------------------------
__device__ __forceinline__ void rope_sc(int pos, float fi, float& sn, float& cs)
{
    double f = (double)pos * (double)fi;
    double k = floor(f * 0.15915494309189535);
    float fr = (float)(f - k * 6.283185307179586);
    sincosf(fr, &sn, &cs);
}

// ---------------------------------------------------------------------------
// Kernel 2: QKV projection  C[4096][3072] = X @ W^T + b   (tf32 mma)
// 128x128 block tile, ktile 32, 8 warps (4x2), warp tile 32x64.
// ---------------------------------------------------------------------------
__global__ __launch_bounds__(256) void k_gemm_qkv(
    const float* __restrict__ X,
    const float* __restrict__ Wq, const float* __restrict__ Wk, const float* __restrict__ Wv,
    const float* __restrict__ bq, const float* __restrict__ bk, const float* __restrict__ bv)
{
    __shared__ float As[128][36];
    __shared__ float Bs[128][36];
    int bm = blockIdx.y * 128;
    int bn = blockIdx.x * 128;
    int seg = bn >> 10;
    const float* W    = (seg == 0) ? Wq : ((seg == 1) ? Wk : Wv);
    const float* bias = (seg == 0) ? bq : ((seg == 1) ? bk : bv);
    int nl = bn & 1023;                 // column within this W's 1024 rows
    int tid = threadIdx.x;
    int warp = tid >> 5, lane = tid & 31;
    int wm = warp >> 1, wn = warp & 1;
    int r0 = lane >> 2, c0 = lane & 3;

    float acc[2][8][4];
    #pragma unroll
    for (int mt = 0; mt < 2; mt++)
        #pragma unroll
        for (int nt = 0; nt < 8; nt++)
            #pragma unroll
            for (int r = 0; r < 4; r++) acc[mt][nt][r] = 0.f;

    int lrow = tid >> 3;          // 0..31 per pass
    int lcol = (tid & 7) * 4;     // 0..28

    for (int k0 = 0; k0 < DMODEL; k0 += 32) {
        #pragma unroll
        for (int p = 0; p < 4; p++) {
            int row = p*32 + lrow;
            float4 a = *(const float4*)&X[(size_t)(bm + row)*DMODEL + k0 + lcol];
            float4 w = *(const float4*)&W[(size_t)(nl + row)*DMODEL + k0 + lcol];
            As[row][lcol+0] = t32(a.x); As[row][lcol+1] = t32(a.y);
            As[row][lcol+2] = t32(a.z); As[row][lcol+3] = t32(a.w);
            Bs[row][lcol+0] = t32(w.x); Bs[row][lcol+1] = t32(w.y);
            Bs[row][lcol+2] = t32(w.z); Bs[row][lcol+3] = t32(w.w);
        }
        __syncthreads();
        #pragma unroll
        for (int ks = 0; ks < 4; ks++) {
            int kk = ks*8;
            unsigned a[2][4], b[8][2];
            #pragma unroll
            for (int mt = 0; mt < 2; mt++) {
                int mr = wm*32 + mt*16 + r0;
                a[mt][0] = U(As[mr  ][kk + c0]);
                a[mt][1] = U(As[mr+8][kk + c0]);
                a[mt][2] = U(As[mr  ][kk + 4 + c0]);
                a[mt][3] = U(As[mr+8][kk + 4 + c0]);
            }
            #pragma unroll
            for (int nt = 0; nt < 8; nt++) {
                int nr = wn*64 + nt*8 + r0;
                b[nt][0] = U(Bs[nr][kk + c0]);
                b[nt][1] = U(Bs[nr][kk + 4 + c0]);
            }
            #pragma unroll
            for (int mt = 0; mt < 2; mt++)
                #pragma unroll
                for (int nt = 0; nt < 8; nt++)
                    mma8(acc[mt][nt], a[mt], b[nt]);
        }
        __syncthreads();
    }
    // epilogue
    #pragma unroll
    for (int mt = 0; mt < 2; mt++) {
        #pragma unroll
        for (int nt = 0; nt < 8; nt++) {
            int row = bm + wm*32 + mt*16 + r0;
            int col = bn + wn*64 + nt*8 + 2*c0;
            float bx = bias[col & 1023], by = bias[(col+1) & 1023];
            float2 v0 = { acc[mt][nt][0] + bx, acc[mt][nt][1] + by };
            float2 v1 = { acc[mt][nt][2] + bx, acc[mt][nt][3] + by };
            *(float2*)&g_qkv[(size_t)row*QKVN + col]     = v0;
            *(float2*)&g_qkv[(size_t)(row+8)*QKVN + col] = v1;
        }
    }
}

// ---------------------------------------------------------------------------
// Kernel 3a: RoPE on q -> g_q [BH][T][DH]
// ---------------------------------------------------------------------------
__global__ __launch_bounds__(256) void k_rope_q(const float* __restrict__ invf,
                                                const int* __restrict__ past_len)
{
    int bh = blockIdx.y; int b = bh >> 4; int h = bh & 15;
    int gid = blockIdx.x * 256 + threadIdx.x;
    int i = gid & 31; int t = gid >> 5;
    int cnt = g_counts[b];
    float o0 = 0.f, o1 = 0.f;
    if (t < cnt) {
        int pos = past_len[b] + t;
        float sn, cs; rope_sc(pos, invf[i], sn, cs);
        size_t base = (size_t)(b*TNEW + t) * QKVN + h*DH;
        float x0 = g_qkv[base + i];
        float x1 = g_qkv[base + i + 32];
        o0 = x0*cs - x1*sn;
        o1 = x1*cs + x0*sn;
    }
    size_t qb = ((size_t)bh*TNEW + t) * DH;
    g_q[qb + i]      = o0;
    g_q[qb + i + 32] = o1;
}

// ---------------------------------------------------------------------------
// Kernel 3b: assemble k_total / v_total in d_out
// ---------------------------------------------------------------------------
__global__ __launch_bounds__(256) void k_assemble_kv(
    const float* __restrict__ pastk, const float* __restrict__ pastv,
    const float* __restrict__ invf, const int* __restrict__ past_len,
    float* __restrict__ out)
{
    int bh = blockIdx.y; int b = bh >> 4; int h = bh & 15;
    int gid = blockIdx.x * 256 + threadIdx.x;
    int i = gid & 31; int s = gid >> 5;
    int pl = past_len[b]; int tot = g_totals[b];
    float k0, k1, v0, v1;
    if (s < pl) {
        size_t base = ((size_t)bh*CACHED + s) * DH;
        k0 = pastk[base + i]; k1 = pastk[base + i + 32];
        v0 = pastv[base + i]; v1 = pastv[base + i + 32];
    } else if (s < tot) {
        int t = s - pl;
        size_t m = (size_t)(b*TNEW + t) * QKVN;
        float sn, cs; rope_sc(s, invf[i], sn, cs);
        float x0 = g_qkv[m + 1024 + h*DH + i];
        float x1 = g_qkv[m + 1024 + h*DH + i + 32];
        k0 = x0*cs - x1*sn;
        k1 = x1*cs + x0*sn;
        v0 = g_qkv[m + 2048 + h*DH + i];
        v1 = g_qkv[m + 2048 + h*DH + i + 32];
    } else {
        k0 = k1 = v0 = v1 = 0.f;
    }
    size_t base = ((size_t)bh*TTOTAL + s) * DH;
    out[OFF_K + base + i]      = k0;
    out[OFF_K + base + i + 32] = k1;
    out[OFF_V + base + i]      = v0;
    out[OFF_V + base + i + 32] = v1;
}

// ---------------------------------------------------------------------------
// Kernel 4: flash attention with tf32 mma.
// Block: 128 threads (4 warps), 64 q-rows; warp w owns q rows [w*16,(w+1)*16).
// ---------------------------------------------------------------------------
#define AT 68

__global__ __launch_bounds__(128) void k_attn(const float* __restrict__ kvout)
{
    extern __shared__ float sm[];
    float (*Ks)[AT] = (float(*)[AT])sm;
    float (*Vs)[AT] = (float(*)[AT])(sm + 64*AT);
    float (*Ps)[AT] = (float(*)[AT])(sm + 2*64*AT);   // also Q staging

    int bh = blockIdx.x;
    int b = bh >> 4;
    int qb = blockIdx.y << 6;
    int tid = threadIdx.x;
    int warp = tid >> 5, lane = tid & 31;
    int r0 = lane >> 2, c0 = lane & 3;

    // stage Q (64x64) into Ps, tf32-rounded
    {
        const float* qp = g_q + ((size_t)bh*TNEW + qb) * DH;
        #pragma unroll
        for (int j = 0; j < 8; j++) {
            int id = j*128 + tid;
            int row = id >> 4;
            int c = (id & 15) * 4;
            float4 v = *(const float4*)&qp[(size_t)row*DH + c];
            float4 o = { t32(v.x), t32(v.y), t32(v.z), t32(v.w) };
            *(float4*)&Ps[row][c] = o;
        }
    }
    __syncthreads();

    // Q fragments (warp-local rows)
    unsigned qa[8][4];
    int qr = warp*16 + r0;
    #pragma unroll
    for (int ks = 0; ks < 8; ks++) {
        qa[ks][0] = U(Ps[qr  ][ks*8 + c0]);
        qa[ks][1] = U(Ps[qr+8][ks*8 + c0]);
        qa[ks][2] = U(Ps[qr  ][ks*8 + 4 + c0]);
        qa[ks][3] = U(Ps[qr+8][ks*8 + 4 + c0]);
    }

    float oacc[8][4];
    #pragma unroll
    for (int nt = 0; nt < 8; nt++)
        #pragma unroll
        for (int r = 0; r < 4; r++) oacc[nt][r] = 0.f;
    float mrow0 = -1e30f, mrow1 = -1e30f, lrow0 = 0.f, lrow1 = 0.f;

    int tot = g_totals[b];
    int nkb = (tot + 63) >> 6;
    const float* kbase = kvout + OFF_K + (size_t)bh*TTOTAL*DH;
    const float* vbase = kvout + OFF_V + (size_t)bh*TTOTAL*DH;

    for (int kb = 0; kb < nkb; kb++) {
        __syncthreads();   // prior-iter smem reads done (and Q frags at kb=0)
        // load K,V tiles (64x64 each), tf32-rounded
        {
            const float* kg = kbase + (size_t)kb*64*DH;
            const float* vg = vbase + (size_t)kb*64*DH;
            #pragma unroll
            for (int j = 0; j < 8; j++) {
                int id = j*128 + tid;
                int row = id >> 4;
                int c = (id & 15) * 4;
                float4 kv = *(const float4*)&kg[(size_t)row*DH + c];
                float4 vv = *(const float4*)&vg[(size_t)row*DH + c];
                float4 ko = { t32(kv.x), t32(kv.y), t32(kv.z), t32(kv.w) };
                float4 vo = { t32(vv.x), t32(vv.y), t32(vv.z), t32(vv.w) };
                *(float4*)&Ks[row][c] = ko;
                *(float4*)&Vs[row][c] = vo;
            }
        }
        __syncthreads();

        // S = Q K^T  (warp rows x 64 cols)
        float sacc[8][4];
        #pragma unroll
        for (int nt = 0; nt < 8; nt++)
            #pragma unroll
            for (int r = 0; r < 4; r++) sacc[nt][r] = 0.f;
        #pragma unroll
        for (int ks = 0; ks < 8; ks++) {
            #pragma unroll
            for (int nt = 0; nt < 8; nt++) {
                unsigned bb[2];
                bb[0] = U(Ks[nt*8 + r0][ks*8 + c0]);
                bb[1] = U(Ks[nt*8 + r0][ks*8 + 4 + c0]);
                mma8(sacc[nt], qa[ks], bb);
            }
        }

        // scale + mask + row max
        float ml0 = -1e30f, ml1 = -1e30f;
        #pragma unroll
        for (int nt = 0; nt < 8; nt++) {
            int col = kb*64 + nt*8 + 2*c0;
            bool v0 = col < tot, v1 = (col+1) < tot;
            float s0 = v0 ? sacc[nt][0]*0.125f : -1e30f;
            float s1 = v1 ? sacc[nt][1]*0.125f : -1e30f;
            float s2 = v0 ? sacc[nt][2]*0.125f : -1e30f;
            float s3 = v1 ? sacc[nt][3]*0.125f : -1e30f;
            sacc[nt][0] = s0; sacc[nt][1] = s1; sacc[nt][2] = s2; sacc[nt][3] = s3;
            ml0 = fmaxf(ml0, fmaxf(s0, s1));
            ml1 = fmaxf(ml1, fmaxf(s2, s3));
        }
        ml0 = fmaxf(ml0, __shfl_xor_sync(0xffffffffu, ml0, 1));
        ml0 = fmaxf(ml0, __shfl_xor_sync(0xffffffffu, ml0, 2));
        ml1 = fmaxf(ml1, __shfl_xor_sync(0xffffffffu, ml1, 1));
        ml1 = fmaxf(ml1, __shfl_xor_sync(0xffffffffu, ml1, 2));

        float mn0 = fmaxf(mrow0, ml0), mn1 = fmaxf(mrow1, ml1);
        float e0 = __expf(mrow0 - mn0), e1 = __expf(mrow1 - mn1);
        mrow0 = mn0; mrow1 = mn1;

        float ls0 = 0.f, ls1 = 0.f;
        #pragma unroll
        for (int nt = 0; nt < 8; nt++) {
            float p0 = __expf(sacc[nt][0] - mn0);
            float p1 = __expf(sacc[nt][1] - mn0);
            float p2 = __expf(sacc[nt][2] - mn1);
            float p3 = __expf(sacc[nt][3] - mn1);
            ls0 += p0 + p1; ls1 += p2 + p3;
            float2 w0 = { t32(p0), t32(p1) };
            float2 w1 = { t32(p2), t32(p3) };
            *(float2*)&Ps[warp*16 + r0    ][nt*8 + 2*c0] = w0;
            *(float2*)&Ps[warp*16 + r0 + 8][nt*8 + 2*c0] = w1;
            oacc[nt][0] *= e0; oacc[nt][1] *= e0;
            oacc[nt][2] *= e1; oacc[nt][3] *= e1;
        }
        ls0 += __shfl_xor_sync(0xffffffffu, ls0, 1);
        ls0 += __shfl_xor_sync(0xffffffffu, ls0, 2);
        ls1 += __shfl_xor_sync(0xffffffffu, ls1, 1);
        ls1 += __shfl_xor_sync(0xffffffffu, ls1, 2);
        lrow0 = lrow0*e0 + ls0;
        lrow1 = lrow1*e1 + ls1;
        __syncwarp();

        // O += P V  (P rows are warp-private)
        #pragma unroll
        for (int ks = 0; ks < 8; ks++) {
            unsigned pa[4];
            pa[0] = U(Ps[warp*16 + r0    ][ks*8 + c0]);
            pa[1] = U(Ps[warp*16 + r0 + 8][ks*8 + c0]);
            pa[2] = U(Ps[warp*16 + r0    ][ks*8 + 4 + c0]);
            pa[3] = U(Ps[warp*16 + r0 + 8][ks*8 + 4 + c0]);
            #pragma unroll
            for (int nt = 0; nt < 8; nt++) {
                unsigned bb[2];
                bb[0] = U(Vs[ks*8 + c0    ][nt*8 + r0]);
                bb[1] = U(Vs[ks*8 + 4 + c0][nt*8 + r0]);
                mma8(oacc[nt], pa, bb);
            }
        }
    }

    // finalize
    float inv0 = 1.f / lrow0, inv1 = 1.f / lrow1;
    float* op = g_ctx + ((size_t)b*TNEW + qb + warp*16) * DMODEL + (bh & 15)*DH;
    #pragma unroll
    for (int nt = 0; nt < 8; nt++) {
        int col = nt*8 + 2*c0;
        float2 v0 = { oacc[nt][0]*inv0, oacc[nt][1]*inv0 };
        float2 v1 = { oacc[nt][2]*inv1, oacc[nt][3]*inv1 };
        *(float2*)&op[(size_t)r0*DMODEL + col]       = v0;
        *(float2*)&op[(size_t)(r0+8)*DMODEL + col]   = v1;
    }
}

// ---------------------------------------------------------------------------
// Kernel 5: output projection + valid-token mask (tf32 mma)
// ---------------------------------------------------------------------------
__global__ __launch_bounds__(256) void k_gemm_out(
    const float* __restrict__ Wo, const float* __restrict__ bo,
    float* __restrict__ out)
{
    __shared__ float As[128][36];
    __shared__ float Bs[128][36];
    int bm = blockIdx.y * 128;
    int bn = blockIdx.x * 128;
    int tid = threadIdx.x;
    int warp = tid >> 5, lane = tid & 31;
    int wm = warp >> 1, wn = warp & 1;
    int r0 = lane >> 2, c0 = lane & 3;

    float acc[2][8][4];
    #pragma unroll
    for (int mt = 0; mt < 2; mt++)
        #pragma unroll
        for (int nt = 0; nt < 8; nt++)
            #pragma unroll
            for (int r = 0; r < 4; r++) acc[mt][nt][r] = 0.f;

    int lrow = tid >> 3;
    int lcol = (tid & 7) * 4;

    for (int k0 = 0; k0 < DMODEL; k0 += 32) {
        #pragma unroll
        for (int p = 0; p < 4; p++) {
            int row = p*32 + lrow;
            float4 a = *(const float4*)&g_ctx[(size_t)(bm + row)*DMODEL + k0 + lcol];
            float4 w = *(const float4*)&Wo[(size_t)(bn + row)*DMODEL + k0 + lcol];
            As[row][lcol+0] = t32(a.x); As[row][lcol+1] = t32(a.y);
            As[row][lcol+2] = t32(a.z); As[row][lcol+3] = t32(a.w);
            Bs[row][lcol+0] = t32(w.x); Bs[row][lcol+1] = t32(w.y);
            Bs[row][lcol+2] = t32(w.z); Bs[row][lcol+3] = t32(w.w);
        }
        __syncthreads();
        #pragma unroll
        for (int ks = 0; ks < 4; ks++) {
            int kk = ks*8;
            unsigned a[2][4], b[8][2];
            #pragma unroll
            for (int mt = 0; mt < 2; mt++) {
                int mr = wm*32 + mt*16 + r0;
                a[mt][0] = U(As[mr  ][kk + c0]);
                a[mt][1] = U(As[mr+8][kk + c0]);
                a[mt][2] = U(As[mr  ][kk + 4 + c0]);
                a[mt][3] = U(As[mr+8][kk + 4 + c0]);
            }
            #pragma unroll
            for (int nt = 0; nt < 8; nt++) {
                int nr = wn*64 + nt*8 + r0;
                b[nt][0] = U(Bs[nr][kk + c0]);
                b[nt][1] = U(Bs[nr][kk + 4 + c0]);
            }
            #pragma unroll
            for (int mt = 0; mt < 2; mt++)
                #pragma unroll
                for (int nt = 0; nt < 8; nt++)
                    mma8(acc[mt][nt], a[mt], b[nt]);
        }
        __syncthreads();
    }
    #pragma unroll
    for (int mt = 0; mt < 2; mt++) {
        int row = bm + wm*32 + mt*16 + r0;
        int bb0 = (row)     >> 9, tt0 = (row)     & 511;
        int bb1 = (row + 8) >> 9, tt1 = (row + 8) & 511;
        float m0 = (tt0 < g_counts[bb0]) ? 1.f : 0.f;
        float m1 = (tt1 < g_counts[bb1]) ? 1.f : 0.f;
        #pragma unroll
        for (int nt = 0; nt < 8; nt++) {
            int col = bn + wn*64 + nt*8 + 2*c0;
            float bx = bo[col], by = bo[col+1];
            float2 v0 = { (acc[mt][nt][0] + bx)*m0, (acc[mt][nt][1] + by)*m0 };
            float2 v1 = { (acc[mt][nt][2] + bx)*m1, (acc[mt][nt][3] + by)*m1 };
            *(float2*)&out[(size_t)row*DMODEL + col]     = v0;
            *(float2*)&out[(size_t)(row+8)*DMODEL + col] = v1;
        }
    }
}

// ---------------------------------------------------------------------------
extern "C" void kernel_launch(void* const* d_in, const int* in_sizes, int n_in,
                              void* d_out, int out_size)
{
    const float* x     = (const float*)d_in[0];
    const float* invf  = (const float*)d_in[1];
    const float* pastk = (const float*)d_in[2];
    const float* pastv = (const float*)d_in[3];
    const float* Wq    = (const float*)d_in[4];
    const float* bq    = (const float*)d_in[5];
    const float* Wk    = (const float*)d_in[6];
    const float* bk    = (const float*)d_in[7];
    const float* Wv    = (const float*)d_in[8];
    const float* bv    = (const float*)d_in[9];
    const float* Wo    = (const float*)d_in[10];
    const float* bo    = (const float*)d_in[11];
    const int* past_len = (const int*)d_in[13];
    const unsigned char* vmask = (const unsigned char*)d_in[14];
    float* out = (float*)d_out;

    k_setup<<<B_, 32>>>(vmask, past_len, out + OFF_LEN);
    k_gemm_qkv<<<dim3(QKVN/128, MROWS/128), 256>>>(x, Wq, Wk, Wv, bq, bk, bv);
    k_rope_q<<<dim3(TNEW*32/256, B_*H_), 256>>>(invf, past_len);
    k_assemble_kv<<<dim3(TTOTAL*32/256, B_*H_), 256>>>(pastk, pastv, invf, past_len, out);

    int smem = 3*64*AT*4;  // 52224 bytes
    cudaFuncSetAttribute(k_attn, cudaFuncAttributeMaxDynamicSharedMemorySize, smem);
    k_attn<<<dim3(B_*H_, TNEW/64), 128, smem>>>(out);

    k_gemm_out<<<dim3(DMODEL/128, MROWS/128), 256>>>(Wo, bo, out);
}